// round 14
// baseline (speedup 1.0000x reference)
#include <cuda_runtime.h>

#define NTP 512   // pass threads

// 8 MB state, tables, composed unitaries — all __device__ globals (no allocs).
__device__ float2 g_psi[16 * 65536];
__device__ float2 g_U[240];        // 60 composed 2x2 unitaries
// Factored layer-0 ring-phase tables: phase(i) = lo[i&0x1FF] * hi[(i>>8)&0xFF | (i&1)<<8]
__device__ float2 g_f0lo[512], g_f0hi[512];   // depth 0
__device__ float2 g_f1lo[512], g_f1hi[512];   // depth 1
__device__ float2 g_t1[512];       // layer1 ring phases (2 depths x 256)
__device__ float2 g_t2[32];        // layer2 (2 x 16)
__device__ float2 g_t3[8];         // layer3 (2 x 4)

__device__ __forceinline__ float2 cmul(float2 a, float2 b) {
    return make_float2(fmaf(a.x, b.x, -a.y * b.y), fmaf(a.x, b.y, a.y * b.x));
}
__device__ __forceinline__ float2 cadd(float2 a, float2 b) {
    return make_float2(a.x + b.x, a.y + b.y);
}
__device__ __forceinline__ void mm2(const float2* A, const float2* B, float2* C) {
    C[0] = cadd(cmul(A[0], B[0]), cmul(A[1], B[2]));
    C[1] = cadd(cmul(A[0], B[1]), cmul(A[1], B[3]));
    C[2] = cadd(cmul(A[2], B[0]), cmul(A[3], B[2]));
    C[3] = cadd(cmul(A[2], B[1]), cmul(A[3], B[3]));
}

// Bank-conflict-killing swizzle (involution): XOR low nibble with bits 4-7.
__device__ __forceinline__ int SWZ(int i) { return i ^ ((i >> 4) & 15); }
// Insert a zero bit at position B.
__device__ __forceinline__ int insb(int x, int B) {
    return ((x >> B) << (B + 1)) | (x & ((1 << B) - 1));
}

// Layer-0 factored ring phase lookup (full 16-bit amp index, batch-free).
__device__ __forceinline__ float2 ring0_d0(int i) {
    return cmul(g_f0lo[i & 0x1FF], g_f0hi[((i >> 8) & 0xFF) | ((i & 1) << 8)]);
}
__device__ __forceinline__ float2 ring0_d1(int i) {
    return cmul(g_f1lo[i & 0x1FF], g_f1hi[((i >> 8) & 0xFF) | ((i & 1) << 8)]);
}

// 2x2 gate coefficients + pair application.
struct G4 { float2 a, b, c, d; };
__device__ __forceinline__ G4 ldG(int u) {
    return { g_U[4*u], g_U[4*u+1], g_U[4*u+2], g_U[4*u+3] };
}
__device__ __forceinline__ void gap(const G4& g, float2& x, float2& y) {
    float2 nx = cadd(cmul(g.a, x), cmul(g.b, y));
    float2 ny = cadd(cmul(g.c, x), cmul(g.d, y));
    x = nx; y = ny;
}

// ---------------------------------------------------------------------------
// Prep (tiny): factored ring tables, small ring tables, 60 composed unitaries.
// Ring term j couples amp bits (15-j) and (15-(j+1 mod 16)).
// ---------------------------------------------------------------------------
__global__ __launch_bounds__(512) void prep_kernel(
    const float* __restrict__ p0, const float* __restrict__ p1,
    const float* __restrict__ p2, const float* __restrict__ p3,
    float* __restrict__ out)
{
    int T = blockIdx.x * 512 + threadIdx.x;

    if (T < 512) {                      // lo tables (amp bits 8..0)
        float ph0 = 0.f, ph1 = 0.f;
        #pragma unroll
        for (int j = 7; j < 15; j++) {
            int x = ((T >> (15 - j)) ^ (T >> (14 - j))) & 1;
            float sg = x ? 0.5f : -0.5f;
            ph0 += sg * p0[4 * j + 3];
            ph1 += sg * p0[4 * j + 67];
        }
        g_f0lo[T] = make_float2(cosf(ph0), sinf(ph0));
        g_f1lo[T] = make_float2(cosf(ph1), sinf(ph1));
    } else if (T < 1024) {              // hi tables
        int ih = T - 512;
        float ph0 = 0.f, ph1 = 0.f;
        #pragma unroll
        for (int j = 0; j < 7; j++) {
            int x = ((ih >> (7 - j)) ^ (ih >> (6 - j))) & 1;
            float sg = x ? 0.5f : -0.5f;
            ph0 += sg * p0[4 * j + 3];
            ph1 += sg * p0[4 * j + 67];
        }
        {   // term j=15: amp bits 0 (ih bit 8) and 15 (ih bit 7)
            int x = ((ih >> 8) ^ (ih >> 7)) & 1;
            float sg = x ? 0.5f : -0.5f;
            ph0 += sg * p0[63];
            ph1 += sg * p0[127];
        }
        g_f0hi[ih] = make_float2(cosf(ph0), sinf(ph0));
        g_f1hi[ih] = make_float2(cosf(ph1), sinf(ph1));
    } else if (T < 1536) {              // layer1 ring (8 wires), 2 depths x 256
        int tt = T - 1024;
        int d = tt >> 8, idx = tt & 255;
        float ph = 0.f;
        #pragma unroll
        for (int j = 0; j < 8; j++) {
            int jn = (j + 1) & 7;
            int x = ((idx >> (7 - j)) ^ (idx >> (7 - jn))) & 1;
            ph += (x ? 0.5f : -0.5f) * p1[4 * j + 3 + 32 * d];
        }
        g_t1[tt] = make_float2(cosf(ph), sinf(ph));
    } else if (T < 1568) {              // layer2 ring (4 wires)
        int tt = T - 1536;
        int d = tt >> 4, idx = tt & 15;
        float ph = 0.f;
        #pragma unroll
        for (int j = 0; j < 4; j++) {
            int jn = (j + 1) & 3;
            int x = ((idx >> (3 - j)) ^ (idx >> (3 - jn))) & 1;
            ph += (x ? 0.5f : -0.5f) * p2[4 * j + 3 + 16 * d];
        }
        g_t2[tt] = make_float2(cosf(ph), sinf(ph));
    } else if (T < 1576) {              // layer3 (2 wires)
        int tt = T - 1568;
        int d = tt >> 2, idx = tt & 3;
        int x = ((idx >> 1) ^ idx) & 1;
        float sg = x ? 0.5f : -0.5f;
        float ph = sg * (p3[3 + 8 * d] + p3[7 + 8 * d]);
        g_t3[tt] = make_float2(cosf(ph), sinf(ph));
    } else if (T >= 1600 && T < 1660) { // compose 60 unitaries U = RX(c)*RZ(b)*RX(a)
        int t = T - 1600;
        const float* pp; int base;
        if (t < 32)      { pp = p0; int d = t >> 4;        int s = t & 15;       base = 4 * s + 64 * d; }
        else if (t < 48) { pp = p1; int d = (t - 32) >> 3; int s = (t - 32) & 7; base = 4 * s + 32 * d; }
        else if (t < 56) { pp = p2; int d = (t - 48) >> 2; int s = (t - 48) & 3; base = 4 * s + 16 * d; }
        else             { pp = p3; int d = (t - 56) >> 1; int s = (t - 56) & 1; base = 4 * s + 8 * d; }
        float a = pp[base] * 0.5f, b = pp[base + 1] * 0.5f, c = pp[base + 2] * 0.5f;
        float ca = cosf(a), sa = sinf(a);
        float cb = cosf(b), sb = sinf(b);
        float cc = cosf(c), sc = sinf(c);
        float2 RXa[4] = { {ca,0.f}, {0.f,-sa}, {0.f,-sa}, {ca,0.f} };
        float2 RZb[4] = { {cb,-sb}, {0.f,0.f}, {0.f,0.f}, {cb,sb} };
        float2 RXc[4] = { {cc,0.f}, {0.f,-sc}, {0.f,-sc}, {cc,0.f} };
        float2 M[4], U[4];
        mm2(RZb, RXa, M);
        mm2(RXc, M, U);
        g_U[t * 4 + 0] = U[0]; g_U[t * 4 + 1] = U[1];
        g_U[t * 4 + 2] = U[2]; g_U[t * 4 + 3] = U[3];
    } else if (T >= 1664 && T < 1680) {
        out[T - 1664] = 0.f;
    }
}

// ---------------------------------------------------------------------------
// 3-gate cell sweep: gates u2/u1/u0 on local bits Q2>Q1>Q0. One 8-amp cell
// per thread (512 cells), all loads batched (MLP=8), one round trip.
// WL=true requires Q2<8 (cells inside the thread's warp 256-amp region).
// ---------------------------------------------------------------------------
template<int Q2, int Q1, int Q0, bool WL, class LDF, class STF>
__device__ __forceinline__ void sweep3(int u2, int u1, int u0, LDF ld, STF st) {
    int base;
    if (WL) {
        int w = (int)threadIdx.x >> 5, l = (int)threadIdx.x & 31;
        base = (w << 8) | insb(insb(insb(l, Q0), Q1), Q2);
    } else {
        base = insb(insb(insb((int)threadIdx.x, Q0), Q1), Q2);
    }
    int idx[8]; float2 a[8];
    #pragma unroll
    for (int b = 0; b < 8; b++) {
        idx[b] = base | ((b & 1) << Q0) | (((b >> 1) & 1) << Q1) | ((b >> 2) << Q2);
        a[b] = ld(idx[b]);
    }
    { G4 A = ldG(u0); gap(A,a[0],a[1]); gap(A,a[2],a[3]); gap(A,a[4],a[5]); gap(A,a[6],a[7]); }
    { G4 B = ldG(u1); gap(B,a[0],a[2]); gap(B,a[1],a[3]); gap(B,a[4],a[6]); gap(B,a[5],a[7]); }
    { G4 C = ldG(u2); gap(C,a[0],a[4]); gap(C,a[1],a[5]); gap(C,a[2],a[6]); gap(C,a[3],a[7]); }
    #pragma unroll
    for (int b = 0; b < 8; b++) st(idx[b], a[b]);
}

// Combo: pre-gate upre on Q2, then elementwise diag ph, then gates u2/u1/u0.
template<int Q2, int Q1, int Q0, class PHF, class LDF, class STF>
__device__ __forceinline__ void sweep3c(int upre, int u2, int u1, int u0,
                                        PHF ph, LDF ld, STF st) {
    int base = insb(insb(insb((int)threadIdx.x, Q0), Q1), Q2);
    int idx[8]; float2 a[8];
    #pragma unroll
    for (int b = 0; b < 8; b++) {
        idx[b] = base | ((b & 1) << Q0) | (((b >> 1) & 1) << Q1) | ((b >> 2) << Q2);
        a[b] = ld(idx[b]);
    }
    { G4 P = ldG(upre); gap(P,a[0],a[4]); gap(P,a[1],a[5]); gap(P,a[2],a[6]); gap(P,a[3],a[7]); }
    #pragma unroll
    for (int b = 0; b < 8; b++) a[b] = cmul(a[b], ph(idx[b]));
    { G4 A = ldG(u0); gap(A,a[0],a[1]); gap(A,a[2],a[3]); gap(A,a[4],a[5]); gap(A,a[6],a[7]); }
    { G4 B = ldG(u1); gap(B,a[0],a[2]); gap(B,a[1],a[3]); gap(B,a[4],a[6]); gap(B,a[5],a[7]); }
    { G4 C = ldG(u2); gap(C,a[0],a[4]); gap(C,a[1],a[5]); gap(C,a[2],a[6]); gap(C,a[3],a[7]); }
    #pragma unroll
    for (int b = 0; b < 8; b++) st(idx[b], a[b]);
}

// 1-bit combo: gate upre on Q0, diag ph, gate upost on Q0. 4 cells/thread.
template<int Q0, class PHF, class LDF, class STF>
__device__ __forceinline__ void sweep1c(int upre, int upost, PHF ph, LDF ld, STF st) {
    G4 P = ldG(upre), Q = ldG(upost);
    int i0[4], i1[4]; float2 x[4], y[4];
    #pragma unroll
    for (int k = 0; k < 4; k++) {
        int c = (int)threadIdx.x + k * NTP;
        i0[k] = insb(c, Q0); i1[k] = i0[k] | (1 << Q0);
        x[k] = ld(i0[k]); y[k] = ld(i1[k]);
    }
    #pragma unroll
    for (int k = 0; k < 4; k++) {
        gap(P, x[k], y[k]);
        x[k] = cmul(x[k], ph(i0[k]));
        y[k] = cmul(y[k], ph(i1[k]));
        gap(Q, x[k], y[k]);
        st(i0[k], x[k]); st(i1[k], y[k]);
    }
}

// Layer-3 tail: gates u0h/u0l (d0) on QH/QL, diag ph, gates u1h/u1l (d1),
// then Z-measurement on QH. 2 cells of 4 per thread. No stores.
template<int QH, int QL, class PHF, class LDF>
__device__ __forceinline__ float sweep2m(int u0h, int u0l, int u1h, int u1l,
                                         PHF ph, LDF ld) {
    G4 A = ldG(u0h), B = ldG(u0l), C = ldG(u1h), D = ldG(u1l);
    float acc = 0.f;
    int id[2][4]; float2 a[2][4];
    #pragma unroll
    for (int k = 0; k < 2; k++) {
        int c = (int)threadIdx.x + k * NTP;
        int base = insb(insb(c, QL), QH);
        id[k][0] = base;            id[k][1] = base | (1 << QL);
        id[k][2] = base | (1 << QH); id[k][3] = id[k][2] | (1 << QL);
        #pragma unroll
        for (int j = 0; j < 4; j++) a[k][j] = ld(id[k][j]);
    }
    #pragma unroll
    for (int k = 0; k < 2; k++) {
        gap(A, a[k][0], a[k][2]); gap(A, a[k][1], a[k][3]);   // d0 on QH
        gap(B, a[k][0], a[k][1]); gap(B, a[k][2], a[k][3]);   // d0 on QL
        #pragma unroll
        for (int j = 0; j < 4; j++) a[k][j] = cmul(a[k][j], ph(id[k][j]));
        gap(C, a[k][0], a[k][2]); gap(C, a[k][1], a[k][3]);   // d1 on QH
        gap(D, a[k][0], a[k][1]); gap(D, a[k][2], a[k][3]);   // d1 on QL
        acc += fmaf(a[k][0].x, a[k][0].x, a[k][0].y * a[k][0].y);
        acc += fmaf(a[k][1].x, a[k][1].x, a[k][1].y * a[k][1].y);
        acc -= fmaf(a[k][2].x, a[k][2].x, a[k][2].y * a[k][2].y);
        acc -= fmaf(a[k][3].x, a[k][3].x, a[k][3].y * a[k][3].y);
    }
    return acc;
}

// ---------------------------------------------------------------------------
// 2-gate cell sweep (R13): gate uh on BH, ul on BL (BH > BL). MLP=8.
// ---------------------------------------------------------------------------
template<int BH, int BL, bool WL, class LDF, class STF>
__device__ __forceinline__ void sweep2(int uh, int ul, LDF ld, STF st) {
    G4 H = ldG(uh), L = ldG(ul);
    int b0, b1;
    if (WL) {
        int w = (int)threadIdx.x >> 5, l = (int)threadIdx.x & 31;
        b0 = (w << 8) | insb(insb(l, BL), BH);
        b1 = (w << 8) | insb(insb(l + 32, BL), BH);
    } else {
        b0 = insb(insb((int)threadIdx.x, BL), BH);
        b1 = insb(insb((int)threadIdx.x + NTP, BL), BH);
    }
    int j0 = b0 | (1 << BL), k0 = b0 | (1 << BH), m0 = k0 | (1 << BL);
    int j1 = b1 | (1 << BL), k1 = b1 | (1 << BH), m1 = k1 | (1 << BL);
    float2 a0 = ld(b0), a1 = ld(j0), a2 = ld(k0), a3 = ld(m0);
    float2 c0 = ld(b1), c1 = ld(j1), c2 = ld(k1), c3 = ld(m1);
    gap(L, a0, a1); gap(L, a2, a3); gap(H, a0, a2); gap(H, a1, a3);
    st(b0, a0); st(j0, a1); st(k0, a2); st(m0, a3);
    gap(L, c0, c1); gap(L, c2, c3); gap(H, c0, c2); gap(H, c1, c3);
    st(b1, c0); st(j1, c1); st(k1, c2); st(m1, c3);
}

// ---------------------------------------------------------------------------
// Fused diagonal + CNOT-layer permutation (XOR involution). new[l]=old[p]*ph(p).
// ---------------------------------------------------------------------------
template<class FXF, class PHF>
__device__ __forceinline__ void perm_ph(float2* s, FXF fx, PHF ph) {
    #pragma unroll
    for (int i = 0; i < 8; i++) {
        int l = threadIdx.x + i * NTP;
        int f = fx(l);
        int p = l ^ f;
        if (f == 0) {
            s[SWZ(l)] = cmul(s[SWZ(l)], ph(l));
        } else if (l < p) {
            float2 a = s[SWZ(l)], b = s[SWZ(p)];
            s[SWZ(l)] = cmul(b, ph(p));
            s[SWZ(p)] = cmul(a, ph(l));
        }
    }
    __syncthreads();
}

// ---------------------------------------------------------------------------
// Pass 1: local = amp bits 0..11 (wires 4..15). Layer0 d0 on wires 4..15.
// Local bit b holds wire 15-b -> U(15-b).
// ---------------------------------------------------------------------------
__global__ __launch_bounds__(NTP, 2) void pass1_kernel(
    const float* __restrict__ xre, const float* __restrict__ xim)
{
    __shared__ float2 s[4096];
    int b = blockIdx.x >> 4, tile = blockIdx.x & 15;
    int base = (b << 16) | (tile << 12);
    auto SLD = [&](int l) { return s[SWZ(l)]; };
    auto SST = [&](int l, float2 v) { s[SWZ(l)] = v; };
    sweep3<11, 10, 9, false>(4, 5, 6,
        [&](int l) { return make_float2(xre[base + l], xim[base + l]); }, SST);
    __syncthreads();
    sweep3<8, 7, 6, false>(7, 8, 9, SLD, SST);   __syncthreads();
    sweep3<5, 4, 3, true>(10, 11, 12, SLD, SST); __syncwarp();
    sweep3<2, 1, 0, true>(13, 14, 15, SLD,
        [&](int l, float2 v) { g_psi[base + l] = v; });
}

// ---------------------------------------------------------------------------
// Pass 2: local amp bits {0-4,7,9,11,12-15}. Global amp bits {5,6,8,10}.
// Locals: l11=w0 l10=w1 l9=w2 l8=w3 l7=w4 l6=w6 l5=w8 l4=w11 l3..0=w12..15.
// d1 U-map: 16,17,18,19,20,22,24,27,28,29,30,31.
// Combo sweep applies the last d0 gate (U3 on l8), ring-d0 diag, then d1
// gates on l8,l7,l6 — all in one round trip.
// ---------------------------------------------------------------------------
__device__ __forceinline__ int expand2x(int l) {
    return (l & 0x1F) | ((l & 0x20) << 2) | ((l & 0x40) << 3) | ((l & 0xF80) << 4);
}
__global__ __launch_bounds__(NTP, 2) void pass2_kernel() {
    __shared__ float2 s[4096];
    int b = blockIdx.x >> 4, tile = blockIdx.x & 15;
    unsigned tor = ((tile & 3) << 5) | ((tile & 4) << 6) | ((tile & 8) << 7);
    unsigned gb = (unsigned)b << 16;
    auto SLD = [&](int l) { return s[SWZ(l)]; };
    auto SST = [&](int l, float2 v) { s[SWZ(l)] = v; };
    // layer0 d0 on l11,l10,l9 (U0,1,2), fused with global load
    sweep3<11, 10, 9, false>(0, 1, 2,
        [&](int l) { return g_psi[gb | tor | expand2x(l)]; }, SST);
    __syncthreads();
    // U3 (d0 on l8) -> ring D0 diag -> d1 on l8(19), l7(20), l6(22)
    sweep3c<8, 7, 6>(3, 19, 20, 22,
        [&](int l) { return ring0_d0(tor | expand2x(l)); }, SLD, SST);
    __syncthreads();
    sweep3<11, 10, 9, false>(16, 17, 18, SLD, SST); __syncthreads();
    sweep3<5, 4, 3, true>(24, 27, 28, SLD, SST);    __syncwarp();
    sweep3<2, 1, 0, true>(29, 30, 31, SLD,
        [&](int l, float2 v) { g_psi[gb | tor | expand2x(l)] = v; });
}

// ---------------------------------------------------------------------------
// Pass 3 (unchanged from R13): local amp bits {0-6,8,10,12,14,15}.
// Local map: l11=w0 l10=w1 l9=w3 l8=w5 l7=w7 l6=w9 l5=w10 l4..l0=w11..w15.
// ---------------------------------------------------------------------------
__device__ __forceinline__ int expand3x(int l) {
    return (l & 0x7F) | ((l & 0x80) << 1) | ((l & 0x100) << 2) |
           ((l & 0x200) << 3) | ((l & 0xC00) << 4);
}
__global__ __launch_bounds__(NTP, 2) void pass3_kernel() {
    __shared__ float2 s[4096];
    int b = blockIdx.x >> 4, tile = blockIdx.x & 15;
    unsigned tor = ((tile & 1) << 7) | ((tile & 2) << 8) | ((tile & 4) << 9) | ((tile & 8) << 10);
    unsigned gb = (unsigned)b << 16;
    auto SLD = [&](int l) { return s[SWZ(l)]; };
    auto SST = [&](int l, float2 v) { s[SWZ(l)] = v; };
    // layer0 d1 leftovers: w5->l8(U21), w7->l7(U23), w9->l6(U25), w10->l5(U26)
    sweep2<8, 5, false>(21, 26,
        [&](int l) { return g_psi[gb | tor | expand3x(l)]; }, SST);
    __syncthreads();
    sweep2<7, 6, true>(23, 25, SLD, SST); __syncthreads();
    // ring D1 + all 8 pool CNOTs fused (targets l10,l9,l8,l7,l6,l4,l2,l0).
    {
        int fc = (((tile >> 3) & 1) << 9) | (((tile >> 2) & 1) << 8) |
                 (((tile >> 1) & 1) << 7) | ((tile & 1) << 6);
        perm_ph(s,
            [&](int l) {
                return ((((l >> 11) & 1) << 10) | (((l >> 5) & 1) << 4) |
                        (((l >> 3) & 1) << 2) | ((l >> 1) & 1)) | fc;
            },
            [&](int l) { return ring0_d1(tor | expand3x(l)); });
    }
    // layer1 d0 on wires 0,10,12,14 -> locals 11(U32),5(U37),3(U38),1(U39)
    sweep2<11, 1, false>(32, 39, SLD, SST); __syncthreads();
    sweep2<5, 3, true>(37, 38, SLD,
        [&](int l, float2 v) { g_psi[gb | tor | expand3x(l)] = v; });
}

// ---------------------------------------------------------------------------
// Pass 4: local amp bits {0-7,9,11,13,15}. Global amp bits {8,10,12,14}.
// Local map: l11=w0 l10=w2 l9=w4 l8=w6 l7=w8 l5=w10 l3=w12 l1=w14.
// layer1 d1 U-map: l11:40 l10:41 l9:42 l8:43 l7:44 l5:45 l3:46 l1:47.
// Final t3-d1 diag + pool3 CNOT provably don't change <Z(l11)> — dropped.
// ---------------------------------------------------------------------------
__device__ __forceinline__ int expand4x(int l) {
    return (l & 0xFF) | ((l & 0x100) << 1) | ((l & 0x200) << 2) |
           ((l & 0x400) << 3) | ((l & 0x800) << 4);
}
__device__ __forceinline__ int p4_idx8(int l) {
    return ((l >> 4) & 0xF8) | ((l >> 3) & 4) | ((l >> 2) & 2) | ((l >> 1) & 1);
}
__device__ __forceinline__ int p4_idx4(int l) {
    return ((l >> 8) & 8) | ((l >> 7) & 4) | ((l >> 6) & 2) | ((l >> 3) & 1);
}
__device__ __forceinline__ int p4_idx2(int l) {
    return ((l >> 10) & 2) | ((l >> 7) & 1);
}
__global__ __launch_bounds__(NTP, 2) void pass4_kernel(float* __restrict__ out) {
    __shared__ float2 s[4096];
    __shared__ float ws[16];
    int tid = threadIdx.x;
    int b = blockIdx.x >> 4, tile = blockIdx.x & 15;
    unsigned tor = ((tile & 1) << 8) | ((tile & 2) << 9) | ((tile & 4) << 10) | ((tile & 8) << 11);
    unsigned gb = (unsigned)b << 16;
    auto SLD = [&](int l) { return s[SWZ(l)]; };
    auto SST = [&](int l, float2 v) { s[SWZ(l)] = v; };

    // layer1 d0 leftovers on l10(33), l9(34), l8(35), fused with global load
    sweep3<10, 9, 8, false>(33, 34, 35,
        [&](int l) { return g_psi[gb | tor | expand4x(l)]; }, SST);
    __syncthreads();
    // U36 (d0 on l7) -> ring-d0 diag -> d1 on l7(44), l5(45), l3(46)
    sweep3c<7, 5, 3>(36, 44, 45, 46,
        [&](int l) { return g_t1[p4_idx8(l)]; }, SLD, SST);
    __syncthreads();
    sweep3<11, 10, 9, false>(40, 41, 42, SLD, SST); __syncthreads();
    sweep2<8, 1, false>(43, 47, SLD, SST);          __syncthreads();
    // ring d1 + layer1 pool (l10<-l11, l8<-l9, l5<-l7, l1<-l3)
    perm_ph(s,
        [&](int l) {
            return (((l >> 11) & 1) << 10) | (((l >> 9) & 1) << 8) |
                   (((l >> 7) & 1) << 5) | (((l >> 3) & 1) << 1);
        },
        [&](int l) { return g_t1[256 + p4_idx8(l)]; });

    // layer2 d0 on l11(48), l9(49), l7(50)
    sweep3<11, 9, 7, false>(48, 49, 50, SLD, SST); __syncthreads();
    // U51 (d0 on l3) -> ring-d0 diag -> d1 on l3(55)
    sweep1c<3>(51, 55, [&](int l) { return g_t2[p4_idx4(l)]; }, SLD, SST);
    __syncthreads();
    sweep3<11, 9, 7, false>(52, 53, 54, SLD, SST); __syncthreads();
    // ring d1 + layer2 pool (l9<-l11, l3<-l7)
    perm_ph(s,
        [&](int l) {
            return (((l >> 11) & 1) << 9) | (((l >> 7) & 1) << 3);
        },
        [&](int l) { return g_t2[16 + p4_idx4(l)]; });

    // layer3 in ONE sweep: U56/U57 (d0), t3-d0 diag, U58/U59 (d1), measure Z(l11).
    float acc = sweep2m<11, 7>(56, 57, 58, 59,
        [&](int l) { return g_t3[p4_idx2(l)]; }, SLD);

    #pragma unroll
    for (int o = 16; o > 0; o >>= 1) acc += __shfl_xor_sync(0xFFFFFFFFu, acc, o);
    if ((tid & 31) == 0) ws[tid >> 5] = acc;
    __syncthreads();
    if (tid == 0) {
        float t = 0.f;
        #pragma unroll
        for (int k = 0; k < 16; k++) t += ws[k];
        atomicAdd(&out[b], t);
    }
}

// ---------------------------------------------------------------------------
extern "C" void kernel_launch(void* const* d_in, const int* in_sizes, int n_in,
                              void* d_out, int out_size) {
    const float* xre = (const float*)d_in[0];
    const float* xim = (const float*)d_in[1];
    const float* p0  = (const float*)d_in[2];
    const float* p1  = (const float*)d_in[3];
    const float* p2  = (const float*)d_in[4];
    const float* p3  = (const float*)d_in[5];
    float* out = (float*)d_out;

    prep_kernel<<<8, 512>>>(p0, p1, p2, p3, out);
    pass1_kernel<<<256, NTP>>>(xre, xim);
    pass2_kernel<<<256, NTP>>>();
    pass3_kernel<<<256, NTP>>>();
    pass4_kernel<<<256, NTP>>>(out);
}